// round 7
// baseline (speedup 1.0000x reference)
#include <cuda_runtime.h>
#include <cuda_fp16.h>
#include <cstdint>

// Problem constants (fixed by dataset: B=4, S=2048, D=1024, O=1024, C=8)
#define T_TOK 8192
#define DIM_D 1024
#define DIM_O 1024
#define N_CAT 8

#define TM 128
#define TN 256
#define BK 64                        // K per smem stage (64 fp16 = 128B rows)
#define NCHUNK (DIM_D / BK)          // 16
#define MAX_TILES (T_TOK / TM + N_CAT)

// ---------------- device scratch (no allocation allowed) --------------------
__device__ int g_perm[T_TOK];
__device__ int g_tile_cat[MAX_TILES];
__device__ int g_tile_row[MAX_TILES];
__device__ int g_tile_rows[MAX_TILES];
__device__ int g_n_tiles;

// fp16 operands. A padded by TM rows: padding never written -> stays zero
// (module zero init) -> safe for partial tiles.
__device__ __half g_Xh[(T_TOK + TM) * DIM_D];
__device__ __half g_Wh[N_CAT * DIM_O * DIM_D];   // transposed: [c][o][d]

// ---------------- PTX helpers (baseline sm_80/75 features only) -------------
__device__ __forceinline__ uint32_t smem_u32(const void* p) {
    uint32_t a;
    asm("{ .reg .u64 t; cvta.to.shared.u64 t, %1; cvt.u32.u64 %0, t; }" : "=r"(a) : "l"(p));
    return a;
}

#define CP_ASYNC16(dst, src) \
    asm volatile("cp.async.cg.shared.global [%0], [%1], 16;" :: "r"(dst), "l"(src) : "memory")
#define CP_COMMIT() asm volatile("cp.async.commit_group;" ::: "memory")
#define CP_WAIT0()  asm volatile("cp.async.wait_group 0;" ::: "memory")
#define CP_WAIT1()  asm volatile("cp.async.wait_group 1;" ::: "memory")

#define LDSM4(r0, r1, r2, r3, addr)                                              \
    asm volatile("ldmatrix.sync.aligned.m8n8.x4.shared.b16 {%0,%1,%2,%3}, [%4];" \
                 : "=r"(r0), "=r"(r1), "=r"(r2), "=r"(r3) : "r"(addr))

#define MMA_F16(c, a, b)                                                         \
    asm volatile("mma.sync.aligned.m16n8k16.row.col.f32.f16.f16.f32 "            \
                 "{%0,%1,%2,%3}, {%4,%5,%6,%7}, {%8,%9}, {%0,%1,%2,%3};"         \
                 : "+f"((c)[0]), "+f"((c)[1]), "+f"((c)[2]), "+f"((c)[3])        \
                 : "r"((a)[0]), "r"((a)[1]), "r"((a)[2]), "r"((a)[3]),           \
                   "r"((b)[0]), "r"((b)[1]))

__device__ __forceinline__ uint32_t sw128(uint32_t off) {
    return off ^ ((off >> 3) & 0x70);
}

// ---------------- fused setup: hist + scan + tiles + perm (one CTA) ---------
__global__ void k_setup(const int* __restrict__ cid) {
    __shared__ int s_cnt[N_CAT], s_cur[N_CAT], s_off[N_CAT];
    const int tid = threadIdx.x;    // 1024 threads
    if (tid < N_CAT) { s_cnt[tid] = 0; s_cur[tid] = 0; }
    __syncthreads();

    int cl[8];
#pragma unroll
    for (int i = 0; i < 8; i++) {
        cl[i] = cid[tid + i * 1024] & (N_CAT - 1);
        atomicAdd(&s_cnt[cl[i]], 1);
    }
    __syncthreads();

    if (tid == 0) {
        int off = 0, nt = 0;
        for (int c = 0; c < N_CAT; c++) {
            s_off[c] = off;
            int cnt = s_cnt[c];
            for (int r = 0; r < cnt; r += TM) {
                g_tile_cat[nt]  = c;
                g_tile_row[nt]  = off + r;
                g_tile_rows[nt] = (cnt - r < TM) ? (cnt - r) : TM;
                nt++;
            }
            off += cnt;
        }
        g_n_tiles = nt;
    }
    __syncthreads();

#pragma unroll
    for (int i = 0; i < 8; i++) {
        int c = cl[i];
        int pos = s_off[c] + atomicAdd(&s_cur[c], 1);
        g_perm[pos] = tid + i * 1024;
    }
}

// ---------------- x -> sorted-gathered fp16 ---------------------------------
__global__ void k_conv_x(const float* __restrict__ x) {
    const int p   = blockIdx.x;         // sorted position
    const int tok = g_perm[p];
    const int c   = threadIdx.x * 4;    // 256 threads
    float4 v = *reinterpret_cast<const float4*>(x + (size_t)tok * DIM_D + c);

    __half2 a = __floats2half2_rn(v.x, v.y);
    __half2 b = __floats2half2_rn(v.z, v.w);
    uint2 u;
    u.x = *reinterpret_cast<uint32_t*>(&a);
    u.y = *reinterpret_cast<uint32_t*>(&b);
    *reinterpret_cast<uint2*>(&g_Xh[(size_t)p * DIM_D + c]) = u;
}

// ---------------- w [c][d][o] fp32 -> [c][o][d] fp16 (smem transpose) -------
__global__ void k_conv_w(const float* __restrict__ w) {
    __shared__ float t[32][33];
    const int cat = blockIdx.z;
    const int o0  = blockIdx.x * 32;
    const int d0  = blockIdx.y * 32;
    const int tx = threadIdx.x, ty = threadIdx.y;   // (32, 8)

    const float* src = w + ((size_t)cat << 20) + (size_t)d0 * DIM_O + o0;
#pragma unroll
    for (int i = 0; i < 4; i++)
        t[ty + 8 * i][tx] = src[(size_t)(ty + 8 * i) * DIM_O + tx];
    __syncthreads();

    size_t dst = ((size_t)cat << 20) + (size_t)o0 * DIM_D + d0;
#pragma unroll
    for (int i = 0; i < 4; i++)
        g_Wh[dst + (size_t)(ty + 8 * i) * DIM_D + tx] = __float2half_rn(t[tx][ty + 8 * i]);
}

// ---------------- fp16 mma.sync grouped GEMM (128x256 CTA tile) -------------
// smem: [0..512) toks, [512..1536) bias, [2048..) 3 stages of {A 16K | B 32K}
#define SM_TOKS   0
#define SM_BIAS   512
#define SM_STAGE  2048
#define PART_A_BYTES 16384
#define STAGE_BYTES  49152
#define NSTAGE 3
#define SMEM_TOTAL (SM_STAGE + NSTAGE * STAGE_BYTES)

__global__ __launch_bounds__(256)
void k_gemm_f16(const float* __restrict__ bias, float* __restrict__ out) {
    const int tile = blockIdx.x;
    if (tile >= g_n_tiles) return;

    const int cat       = g_tile_cat[tile] & (N_CAT - 1);
    const int row_start = g_tile_row[tile];
    const int rows      = g_tile_rows[tile];
    const int n0        = blockIdx.y * TN;

    extern __shared__ char smem[];
    const uint32_t sm = smem_u32(smem);
    const int tid  = threadIdx.x;
    const int wid  = tid >> 5;
    const int lane = tid & 31;
    const int wm   = wid >> 2;        // 0..1 -> m offset wm*64
    const int wn   = wid & 3;         // 0..3 -> n offset wn*64

    int*   toks   = reinterpret_cast<int*>(smem + SM_TOKS);
    float* bias_s = reinterpret_cast<float*>(smem + SM_BIAS);
    if (tid < TM) toks[tid] = (tid < rows) ? g_perm[row_start + tid] : -1;
    bias_s[tid] = bias[cat * DIM_O + n0 + tid];

    // global row bases (fp16 rows = 2048B)
    const char* gA = reinterpret_cast<const char*>(g_Xh) + (size_t)row_start * 2048;
    const char* gB = reinterpret_cast<const char*>(g_Wh) + (((size_t)cat << 10) + n0) * 2048;

    // chunk loader: A 128 rows + B 256 rows, each 8 x 16B -> 3072 cp.async, 12/thread
#define ISSUE_CHUNK(kc, buf)                                                        \
    _Pragma("unroll")                                                               \
    for (int t = 0; t < 12; t++) {                                                  \
        int idx = tid + t * 256;                                                    \
        uint32_t stg = sm + SM_STAGE + (buf) * STAGE_BYTES;                         \
        if (idx < 1024) {                                                           \
            int r = idx >> 3, c = idx & 7;                                          \
            const char* src = gA + (size_t)r * 2048 + (size_t)(kc) * 128 + c * 16;  \
            CP_ASYNC16(stg + sw128((uint32_t)(r * 128 + c * 16)), src);             \
        } else {                                                                    \
            int i2 = idx - 1024;                                                    \
            int r = i2 >> 3, c = i2 & 7;                                            \
            const char* src = gB + (size_t)r * 2048 + (size_t)(kc) * 128 + c * 16;  \
            CP_ASYNC16(stg + PART_A_BYTES + sw128((uint32_t)(r * 128 + c * 16)), src); \
        }                                                                           \
    }                                                                               \
    CP_COMMIT();

    float acc[4][8][4];
#pragma unroll
    for (int i = 0; i < 4; i++)
#pragma unroll
        for (int j = 0; j < 8; j++)
#pragma unroll
            for (int k = 0; k < 4; k++) acc[i][j][k] = 0.f;

    // prologue: 2 chunks in flight, 3 buffers
    ISSUE_CHUNK(0, 0);
    ISSUE_CHUNK(1, 1);

    const int fr_row = lane & 15;
    const int fr_kb  = lane >> 4;

    for (int it = 0; it < NCHUNK; it++) {
        if (it < NCHUNK - 1) { CP_WAIT1(); } else { CP_WAIT0(); }
        __syncthreads();   // chunk `it` visible; stage (it+2)%3 free

        if (it + 2 < NCHUNK) { ISSUE_CHUNK(it + 2, (it + 2) % NSTAGE); }

        const uint32_t st  = sm + SM_STAGE + (it % NSTAGE) * STAGE_BYTES;
        const uint32_t stA = st;
        const uint32_t stB = st + PART_A_BYTES;

#pragma unroll
        for (int ks = 0; ks < 4; ks++) {
            const uint32_t kcol = (uint32_t)((ks * 2 + fr_kb) * 16);

            uint32_t a[4][4], b[8][2];
#pragma unroll
            for (int mi = 0; mi < 4; mi++) {
                uint32_t ad = sw128((uint32_t)((wm * 64 + mi * 16 + fr_row) * 128) + kcol);
                LDSM4(a[mi][0], a[mi][1], a[mi][2], a[mi][3], stA + ad);
            }
#pragma unroll
            for (int pj = 0; pj < 4; pj++) {
                uint32_t ad = sw128((uint32_t)((wn * 64 + pj * 16 + fr_row) * 128) + kcol);
                uint32_t r0, r1, r2, r3;
                LDSM4(r0, r1, r2, r3, stB + ad);
                b[pj * 2][0]     = r0; b[pj * 2][1]     = r2;
                b[pj * 2 + 1][0] = r1; b[pj * 2 + 1][1] = r3;
            }

#pragma unroll
            for (int mi = 0; mi < 4; mi++)
#pragma unroll
                for (int ni = 0; ni < 8; ni++)
                    MMA_F16(acc[mi][ni], a[mi], b[ni]);
        }
    }

    // ---- epilogue: bias + scatter (C frag: rows t/4, t/4+8; cols 2(t%4)+{0,1})
#pragma unroll
    for (int mi = 0; mi < 4; mi++) {
        int m0   = wm * 64 + mi * 16 + (lane >> 2);
        int tok0 = toks[m0];
        int tok1 = toks[m0 + 8];
#pragma unroll
        for (int ni = 0; ni < 8; ni++) {
            int col = wn * 64 + ni * 8 + 2 * (lane & 3);
            float b0 = bias_s[col], b1 = bias_s[col + 1];
            if (tok0 >= 0) {
                float2 v = make_float2(acc[mi][ni][0] + b0, acc[mi][ni][1] + b1);
                *reinterpret_cast<float2*>(out + (size_t)tok0 * DIM_O + n0 + col) = v;
            }
            if (tok1 >= 0) {
                float2 v = make_float2(acc[mi][ni][2] + b0, acc[mi][ni][3] + b1);
                *reinterpret_cast<float2*>(out + (size_t)tok1 * DIM_O + n0 + col) = v;
            }
        }
    }
}

// ---------------- launch --------------------------------------------------------
extern "C" void kernel_launch(void* const* d_in, const int* in_sizes, int n_in,
                              void* d_out, int out_size) {
    const float* x    = (const float*)d_in[0];   // [T, D] fp32
    const int*   cid  = (const int*)d_in[1];     // [T] int32
    const float* wgt  = (const float*)d_in[2];   // [C, D, O] fp32
    const float* bias = (const float*)d_in[3];   // [C, O] fp32
    float*       out  = (float*)d_out;           // [T, O] fp32

    (void)in_sizes; (void)n_in; (void)out_size;

    cudaFuncSetAttribute(k_gemm_f16, cudaFuncAttributeMaxDynamicSharedMemorySize, SMEM_TOTAL);

    k_setup<<<1, 1024>>>(cid);
    k_conv_x<<<T_TOK, 256>>>(x);
    k_conv_w<<<dim3(DIM_O / 32, DIM_D / 32, N_CAT), dim3(32, 8)>>>(wgt);

    dim3 grid(MAX_TILES, DIM_O / TN);   // 72 x 4; CTAs past g_n_tiles exit early
    k_gemm_f16<<<grid, 256, SMEM_TOTAL>>>(bias, out);
}

// round 8
// speedup vs baseline: 1.1416x; 1.1416x over previous
#include <cuda_runtime.h>
#include <cuda_fp16.h>
#include <cstdint>

// Problem constants (fixed by dataset: B=4, S=2048, D=1024, O=1024, C=8)
#define T_TOK 8192
#define DIM_D 1024
#define DIM_O 1024
#define N_CAT 8

#define TM 128
#define TN 128
#define BK 64                        // K per smem stage
#define NCHUNK (DIM_D / BK)          // 16
#define MAX_TILES (T_TOK / TM + N_CAT)

// ---------------- device scratch (no allocation allowed) --------------------
__device__ int g_perm[T_TOK];
__device__ int g_tile_cat[MAX_TILES];
__device__ int g_tile_row[MAX_TILES];
__device__ int g_tile_rows[MAX_TILES];
__device__ int g_n_tiles;

// fp16 operands. A padded by TM rows: padding never written -> stays zero
// (module zero init) -> safe for partial tiles. W stays in NATIVE [c][d][o]
// order (k-major B via ldmatrix.trans) -> conversion is a pure stream.
__device__ __half g_Xh[(T_TOK + TM) * DIM_D];
__device__ __half g_Wh[N_CAT * DIM_D * DIM_O];   // [c][d][o]

// ---------------- PTX helpers (baseline sm_80/75 features only) -------------
__device__ __forceinline__ uint32_t smem_u32(const void* p) {
    uint32_t a;
    asm("{ .reg .u64 t; cvta.to.shared.u64 t, %1; cvt.u32.u64 %0, t; }" : "=r"(a) : "l"(p));
    return a;
}

#define CP_ASYNC16(dst, src) \
    asm volatile("cp.async.cg.shared.global [%0], [%1], 16;" :: "r"(dst), "l"(src) : "memory")
#define CP_COMMIT() asm volatile("cp.async.commit_group;" ::: "memory")
#define CP_WAIT0()  asm volatile("cp.async.wait_group 0;" ::: "memory")
#define CP_WAIT1()  asm volatile("cp.async.wait_group 1;" ::: "memory")

#define LDSM4(r0, r1, r2, r3, addr)                                              \
    asm volatile("ldmatrix.sync.aligned.m8n8.x4.shared.b16 {%0,%1,%2,%3}, [%4];" \
                 : "=r"(r0), "=r"(r1), "=r"(r2), "=r"(r3) : "r"(addr))

#define LDSM4T(r0, r1, r2, r3, addr)                                                   \
    asm volatile("ldmatrix.sync.aligned.m8n8.x4.trans.shared.b16 {%0,%1,%2,%3}, [%4];" \
                 : "=r"(r0), "=r"(r1), "=r"(r2), "=r"(r3) : "r"(addr))

#define MMA_F16(c, a, b)                                                         \
    asm volatile("mma.sync.aligned.m16n8k16.row.col.f32.f16.f16.f32 "            \
                 "{%0,%1,%2,%3}, {%4,%5,%6,%7}, {%8,%9}, {%0,%1,%2,%3};"         \
                 : "+f"((c)[0]), "+f"((c)[1]), "+f"((c)[2]), "+f"((c)[3])        \
                 : "r"((a)[0]), "r"((a)[1]), "r"((a)[2]), "r"((a)[3]),           \
                   "r"((b)[0]), "r"((b)[1]))

__device__ __forceinline__ uint32_t sw128(uint32_t off) {
    return off ^ ((off >> 3) & 0x70);
}

// ---------------- fused setup: hist + scan + tiles + perm (one CTA) ---------
__global__ void k_setup(const int* __restrict__ cid) {
    __shared__ int s_cnt[N_CAT], s_cur[N_CAT], s_off[N_CAT];
    const int tid = threadIdx.x;    // 1024 threads
    if (tid < N_CAT) { s_cnt[tid] = 0; s_cur[tid] = 0; }
    __syncthreads();

    int cl[8];
#pragma unroll
    for (int i = 0; i < 8; i++) {
        cl[i] = cid[tid + i * 1024] & (N_CAT - 1);
        atomicAdd(&s_cnt[cl[i]], 1);
    }
    __syncthreads();

    if (tid == 0) {
        int off = 0, nt = 0;
        for (int c = 0; c < N_CAT; c++) {
            s_off[c] = off;
            int cnt = s_cnt[c];
            for (int r = 0; r < cnt; r += TM) {
                g_tile_cat[nt]  = c;
                g_tile_row[nt]  = off + r;
                g_tile_rows[nt] = (cnt - r < TM) ? (cnt - r) : TM;
                nt++;
            }
            off += cnt;
        }
        g_n_tiles = nt;
    }
    __syncthreads();

#pragma unroll
    for (int i = 0; i < 8; i++) {
        int c = cl[i];
        int pos = s_off[c] + atomicAdd(&s_cur[c], 1);
        g_perm[pos] = tid + i * 1024;
    }
}

// ---------------- x -> sorted-gathered fp16 ---------------------------------
__global__ void k_conv_x(const float* __restrict__ x) {
    const int p   = blockIdx.x;         // sorted position
    const int tok = g_perm[p];
    const int c   = threadIdx.x * 4;    // 256 threads
    float4 v = *reinterpret_cast<const float4*>(x + (size_t)tok * DIM_D + c);

    __half2 a = __floats2half2_rn(v.x, v.y);
    __half2 b = __floats2half2_rn(v.z, v.w);
    uint2 u;
    u.x = *reinterpret_cast<uint32_t*>(&a);
    u.y = *reinterpret_cast<uint32_t*>(&b);
    *reinterpret_cast<uint2*>(&g_Xh[(size_t)p * DIM_D + c]) = u;
}

// ---------------- w fp32 -> fp16 (pure streaming, no transpose) -------------
__global__ void k_conv_w(const float* __restrict__ w) {
    const size_t i = ((size_t)blockIdx.x * blockDim.x + threadIdx.x) * 4;
    float4 v = *reinterpret_cast<const float4*>(w + i);
    __half2 a = __floats2half2_rn(v.x, v.y);
    __half2 b = __floats2half2_rn(v.z, v.w);
    uint2 u;
    u.x = *reinterpret_cast<uint32_t*>(&a);
    u.y = *reinterpret_cast<uint32_t*>(&b);
    *reinterpret_cast<uint2*>(&g_Wh[i]) = u;
}

// ---------------- fp16 mma.sync grouped GEMM --------------------------------
// smem: [0..512) toks, [512..1024) bias, [2048..) 3 stages of
// {A: 128 rows x 128B (sw128) | B: 64 k-rows x 256B (xor-8 16B-block swizzle)}
#define SM_TOKS   0
#define SM_BIAS   512
#define SM_STAGE  2048
#define PART_A_BYTES 16384
#define STAGE_BYTES  32768
#define NSTAGE 3
#define SMEM_TOTAL (SM_STAGE + NSTAGE * STAGE_BYTES)

__global__ __launch_bounds__(256, 2)
void k_gemm_f16(const float* __restrict__ bias, float* __restrict__ out) {
    const int tile = blockIdx.x;
    if (tile >= g_n_tiles) return;

    const int cat       = g_tile_cat[tile] & (N_CAT - 1);
    const int row_start = g_tile_row[tile];
    const int rows      = g_tile_rows[tile];
    const int n0        = blockIdx.y * TN;

    extern __shared__ char smem[];
    const uint32_t sm = smem_u32(smem);
    const int tid  = threadIdx.x;
    const int wid  = tid >> 5;
    const int lane = tid & 31;
    const int wm   = wid >> 2;        // 0..1 -> m offset wm*64
    const int wn   = wid & 3;         // 0..3 -> n offset wn*32

    int*   toks   = reinterpret_cast<int*>(smem + SM_TOKS);
    float* bias_s = reinterpret_cast<float*>(smem + SM_BIAS);
    if (tid < TM) toks[tid] = (tid < rows) ? g_perm[row_start + tid] : -1;
    if (tid >= 128) bias_s[tid - 128] = bias[cat * DIM_O + n0 + tid - 128];

    // global bases
    const char* gA = reinterpret_cast<const char*>(g_Xh) + (size_t)row_start * 2048;  // 2048B rows
    const char* gB = reinterpret_cast<const char*>(g_Wh) + ((size_t)(cat << 10) + n0) * 2048 / 1024 * 1024;
    // ^ simplify below: byte offset = (cat*1M + n0) * 2
    gB = reinterpret_cast<const char*>(g_Wh) + (((size_t)cat << 20) + n0) * 2;

    // chunk loader: A 128 rows x 8 x 16B + B 64 k-rows x 16 x 16B = 2048, 8/thread
#define ISSUE_CHUNK(kc, buf)                                                        \
    _Pragma("unroll")                                                               \
    for (int t = 0; t < 8; t++) {                                                   \
        int idx = tid + t * 256;                                                    \
        uint32_t stg = sm + SM_STAGE + (buf) * STAGE_BYTES;                         \
        if (idx < 1024) {                                                           \
            int r = idx >> 3, c = idx & 7;                                          \
            const char* src = gA + (size_t)r * 2048 + (size_t)(kc) * 128 + c * 16;  \
            CP_ASYNC16(stg + sw128((uint32_t)(r * 128 + c * 16)), src);             \
        } else {                                                                    \
            int i2 = idx - 1024;                                                    \
            int r = i2 >> 4, c = i2 & 15;    /* r = k row 0..63, c = 16B block */   \
            const char* src = gB + (size_t)((kc) * BK + r) * 2048 + c * 16;         \
            CP_ASYNC16(stg + PART_A_BYTES + (uint32_t)(r * 256 + ((c ^ (r & 7)) * 16)), src); \
        }                                                                           \
    }                                                                               \
    CP_COMMIT();

    float acc[4][4][4];
#pragma unroll
    for (int i = 0; i < 4; i++)
#pragma unroll
        for (int j = 0; j < 4; j++)
#pragma unroll
            for (int k = 0; k < 4; k++) acc[i][j][k] = 0.f;

    ISSUE_CHUNK(0, 0);
    ISSUE_CHUNK(1, 1);

    const int fr_row = lane & 15;
    const int fr_kb  = lane >> 4;
    // B trans-LDSM per-lane address parts: k_local within 16, and n 16B-block
    const int bk_loc = (lane & 7) + ((lane >> 3) & 1) * 8;   // 0..15
    const int bn_blk = (lane >> 4);                           // 0/1 -> +8 n

    for (int it = 0; it < NCHUNK; it++) {
        if (it < NCHUNK - 1) { CP_WAIT1(); } else { CP_WAIT0(); }
        __syncthreads();

        if (it + 2 < NCHUNK) { ISSUE_CHUNK(it + 2, (it + 2) % NSTAGE); }

        const uint32_t st  = sm + SM_STAGE + (it % NSTAGE) * STAGE_BYTES;
        const uint32_t stA = st;
        const uint32_t stB = st + PART_A_BYTES;

#pragma unroll
        for (int ks = 0; ks < 4; ks++) {
            const uint32_t kcol = (uint32_t)((ks * 2 + fr_kb) * 16);

            uint32_t a[4][4], b[4][2];
#pragma unroll
            for (int mi = 0; mi < 4; mi++) {
                uint32_t ad = sw128((uint32_t)((wm * 64 + mi * 16 + fr_row) * 128) + kcol);
                LDSM4(a[mi][0], a[mi][1], a[mi][2], a[mi][3], stA + ad);
            }
            // B: k-major tile, ldmatrix.trans. Each LDSM4T covers 16k x 16n.
#pragma unroll
            for (int pj = 0; pj < 2; pj++) {
                int k   = ks * 16 + bk_loc;                       // k row in tile
                int blk = wn * 4 + pj * 2 + bn_blk;               // 16B block (8 n)
                uint32_t ad = (uint32_t)(k * 256 + ((blk ^ (k & 7)) * 16));
                uint32_t r0, r1, r2, r3;
                LDSM4T(r0, r1, r2, r3, stB + ad);
                b[pj * 2][0]     = r0; b[pj * 2][1]     = r1;     // n sub 0-7
                b[pj * 2 + 1][0] = r2; b[pj * 2 + 1][1] = r3;     // n sub 8-15
            }

#pragma unroll
            for (int mi = 0; mi < 4; mi++)
#pragma unroll
                for (int ni = 0; ni < 4; ni++)
                    MMA_F16(acc[mi][ni], a[mi], b[ni]);
        }
    }

    // ---- epilogue: bias + scatter
#pragma unroll
    for (int mi = 0; mi < 4; mi++) {
        int m0   = wm * 64 + mi * 16 + (lane >> 2);
        int tok0 = toks[m0];
        int tok1 = toks[m0 + 8];
#pragma unroll
        for (int ni = 0; ni < 4; ni++) {
            int col = wn * 32 + ni * 8 + 2 * (lane & 3);
            float b0 = bias_s[col], b1 = bias_s[col + 1];
            if (tok0 >= 0) {
                float2 v = make_float2(acc[mi][ni][0] + b0, acc[mi][ni][1] + b1);
                *reinterpret_cast<float2*>(out + (size_t)tok0 * DIM_O + n0 + col) = v;
            }
            if (tok1 >= 0) {
                float2 v = make_float2(acc[mi][ni][2] + b0, acc[mi][ni][3] + b1);
                *reinterpret_cast<float2*>(out + (size_t)tok1 * DIM_O + n0 + col) = v;
            }
        }
    }
}

// ---------------- launch --------------------------------------------------------
extern "C" void kernel_launch(void* const* d_in, const int* in_sizes, int n_in,
                              void* d_out, int out_size) {
    const float* x    = (const float*)d_in[0];   // [T, D] fp32
    const int*   cid  = (const int*)d_in[1];     // [T] int32
    const float* wgt  = (const float*)d_in[2];   // [C, D, O] fp32
    const float* bias = (const float*)d_in[3];   // [C, O] fp32
    float*       out  = (float*)d_out;           // [T, O] fp32

    (void)in_sizes; (void)n_in; (void)out_size;

    cudaFuncSetAttribute(k_gemm_f16, cudaFuncAttributeMaxDynamicSharedMemorySize, SMEM_TOTAL);

    k_setup<<<1, 1024>>>(cid);
    k_conv_w<<<(N_CAT * DIM_D * DIM_O / 4) / 256, 256>>>(wgt);
    k_conv_x<<<T_TOK, 256>>>(x);

    dim3 grid(MAX_TILES, DIM_O / TN);   // 72 x 8; CTAs past g_n_tiles exit early
    k_gemm_f16<<<grid, 256, SMEM_TOTAL>>>(bias, out);
}

// round 9
// speedup vs baseline: 1.1735x; 1.0280x over previous
#include <cuda_runtime.h>
#include <cuda_fp16.h>
#include <cstdint>

// Problem constants (fixed by dataset: B=4, S=2048, D=1024, O=1024, C=8)
#define T_TOK 8192
#define DIM_D 1024
#define DIM_O 1024
#define N_CAT 8

#define TM 128
#define TN 128
#define BK 64                        // K per smem stage
#define NCHUNK (DIM_D / BK)          // 16
#define MAX_TILES (T_TOK / TM + N_CAT)

// ---------------- device scratch (no allocation allowed) --------------------
__device__ int g_perm[T_TOK];
__device__ int g_tile_cat[MAX_TILES];
__device__ int g_tile_row[MAX_TILES];
__device__ int g_tile_rows[MAX_TILES];
__device__ int g_n_tiles;

// fp16 operands. A padded by TM rows: padding never written -> stays zero
// (module zero init) -> safe for partial tiles. W stays in NATIVE [c][d][o]
// order (k-major B via ldmatrix.trans) -> conversion is a pure stream.
__device__ __half g_Xh[(T_TOK + TM) * DIM_D];
__device__ __half g_Wh[N_CAT * DIM_D * DIM_O];   // [c][d][o]

// ---------------- PTX helpers (baseline sm_80/75 features only) -------------
__device__ __forceinline__ uint32_t smem_u32(const void* p) {
    uint32_t a;
    asm("{ .reg .u64 t; cvta.to.shared.u64 t, %1; cvt.u32.u64 %0, t; }" : "=r"(a) : "l"(p));
    return a;
}

#define CP_ASYNC16(dst, src) \
    asm volatile("cp.async.cg.shared.global [%0], [%1], 16;" :: "r"(dst), "l"(src) : "memory")
#define CP_COMMIT() asm volatile("cp.async.commit_group;" ::: "memory")
#define CP_WAIT0()  asm volatile("cp.async.wait_group 0;" ::: "memory")
#define CP_WAIT1()  asm volatile("cp.async.wait_group 1;" ::: "memory")

#define LDSM4(r0, r1, r2, r3, addr)                                              \
    asm volatile("ldmatrix.sync.aligned.m8n8.x4.shared.b16 {%0,%1,%2,%3}, [%4];" \
                 : "=r"(r0), "=r"(r1), "=r"(r2), "=r"(r3) : "r"(addr))

#define LDSM4T(r0, r1, r2, r3, addr)                                                   \
    asm volatile("ldmatrix.sync.aligned.m8n8.x4.trans.shared.b16 {%0,%1,%2,%3}, [%4];" \
                 : "=r"(r0), "=r"(r1), "=r"(r2), "=r"(r3) : "r"(addr))

#define MMA_F16(c, a, b)                                                         \
    asm volatile("mma.sync.aligned.m16n8k16.row.col.f32.f16.f16.f32 "            \
                 "{%0,%1,%2,%3}, {%4,%5,%6,%7}, {%8,%9}, {%0,%1,%2,%3};"         \
                 : "+f"((c)[0]), "+f"((c)[1]), "+f"((c)[2]), "+f"((c)[3])        \
                 : "r"((a)[0]), "r"((a)[1]), "r"((a)[2]), "r"((a)[3]),           \
                   "r"((b)[0]), "r"((b)[1]))

__device__ __forceinline__ uint32_t sw128(uint32_t off) {
    return off ^ ((off >> 3) & 0x70);
}

// ---------------- fused setup: hist + scan + tiles + perm (one CTA) ---------
__global__ void k_setup(const int* __restrict__ cid) {
    __shared__ int s_cnt[N_CAT], s_cur[N_CAT], s_off[N_CAT];
    const int tid = threadIdx.x;    // 1024 threads
    if (tid < N_CAT) { s_cnt[tid] = 0; s_cur[tid] = 0; }
    __syncthreads();

    int cl[8];
#pragma unroll
    for (int i = 0; i < 8; i++) {
        cl[i] = cid[tid + i * 1024] & (N_CAT - 1);
        atomicAdd(&s_cnt[cl[i]], 1);
    }
    __syncthreads();

    if (tid == 0) {
        int off = 0, nt = 0;
        for (int c = 0; c < N_CAT; c++) {
            s_off[c] = off;
            int cnt = s_cnt[c];
            for (int r = 0; r < cnt; r += TM) {
                g_tile_cat[nt]  = c;
                g_tile_row[nt]  = off + r;
                g_tile_rows[nt] = (cnt - r < TM) ? (cnt - r) : TM;
                nt++;
            }
            off += cnt;
        }
        g_n_tiles = nt;
    }
    __syncthreads();

#pragma unroll
    for (int i = 0; i < 8; i++) {
        int c = cl[i];
        int pos = s_off[c] + atomicAdd(&s_cur[c], 1);
        g_perm[pos] = tid + i * 1024;
    }
}

// ---------------- merged conversion: W stream-convert + X gather-convert ----
// blocks [0, 8192):  W part — 8M fp32 -> fp16, 1024 elems/block
// blocks [8192, 16384): X part — one sorted token row each (gather via perm)
__global__ void k_convert(const float* __restrict__ w, const float* __restrict__ x) {
    const int b = blockIdx.x;
    if (b < 8192) {
        const size_t i = ((size_t)b * 256 + threadIdx.x) * 4;
        float4 v = *reinterpret_cast<const float4*>(w + i);
        __half2 a = __floats2half2_rn(v.x, v.y);
        __half2 c = __floats2half2_rn(v.z, v.w);
        uint2 u;
        u.x = *reinterpret_cast<uint32_t*>(&a);
        u.y = *reinterpret_cast<uint32_t*>(&c);
        *reinterpret_cast<uint2*>(&g_Wh[i]) = u;
    } else {
        const int p   = b - 8192;           // sorted position
        const int tok = g_perm[p];
        const int c   = threadIdx.x * 4;    // 256 threads
        float4 v = *reinterpret_cast<const float4*>(x + (size_t)tok * DIM_D + c);
        __half2 a = __floats2half2_rn(v.x, v.y);
        __half2 d = __floats2half2_rn(v.z, v.w);
        uint2 u;
        u.x = *reinterpret_cast<uint32_t*>(&a);
        u.y = *reinterpret_cast<uint32_t*>(&d);
        *reinterpret_cast<uint2*>(&g_Xh[(size_t)p * DIM_D + c]) = u;
    }
}

// ---------------- fp16 mma.sync grouped GEMM --------------------------------
// smem: [0..512) toks, [512..1024) bias, [2048..) 3 stages of
// {A: 128 rows x 128B (sw128) | B: 64 k-rows x 256B (xor-8 16B-block swizzle)}
#define SM_TOKS   0
#define SM_BIAS   512
#define SM_STAGE  2048
#define PART_A_BYTES 16384
#define STAGE_BYTES  32768
#define NSTAGE 3
#define SMEM_TOTAL (SM_STAGE + NSTAGE * STAGE_BYTES)

__global__ __launch_bounds__(256, 2)
void k_gemm_f16(const float* __restrict__ bias, float* __restrict__ out) {
    const int tile = blockIdx.x;
    if (tile >= g_n_tiles) return;

    const int cat       = g_tile_cat[tile] & (N_CAT - 1);
    const int row_start = g_tile_row[tile];
    const int rows      = g_tile_rows[tile];
    const int n0        = blockIdx.y * TN;

    extern __shared__ char smem[];
    const uint32_t sm = smem_u32(smem);
    const int tid  = threadIdx.x;
    const int wid  = tid >> 5;
    const int lane = tid & 31;
    const int wm   = wid >> 2;        // 0..1 -> m offset wm*64
    const int wn   = wid & 3;         // 0..3 -> n offset wn*32

    int*   toks   = reinterpret_cast<int*>(smem + SM_TOKS);
    float* bias_s = reinterpret_cast<float*>(smem + SM_BIAS);
    if (tid < TM) toks[tid] = (tid < rows) ? g_perm[row_start + tid] : -1;
    if (tid >= 128) bias_s[tid - 128] = bias[cat * DIM_O + n0 + tid - 128];

    // global bases
    const char* gA = reinterpret_cast<const char*>(g_Xh) + (size_t)row_start * 2048;      // 2048B rows
    const char* gB = reinterpret_cast<const char*>(g_Wh) + (((size_t)cat << 20) + n0) * 2; // [c][d][o] fp16

    // chunk loader: A 128 rows x 8 x 16B + B 64 k-rows x 16 x 16B = 2048, 8/thread
#define ISSUE_CHUNK(kc, buf)                                                        \
    _Pragma("unroll")                                                               \
    for (int t = 0; t < 8; t++) {                                                   \
        int idx = tid + t * 256;                                                    \
        uint32_t stg = sm + SM_STAGE + (buf) * STAGE_BYTES;                         \
        if (idx < 1024) {                                                           \
            int r = idx >> 3, c = idx & 7;                                          \
            const char* src = gA + (size_t)r * 2048 + (size_t)(kc) * 128 + c * 16;  \
            CP_ASYNC16(stg + sw128((uint32_t)(r * 128 + c * 16)), src);             \
        } else {                                                                    \
            int i2 = idx - 1024;                                                    \
            int r = i2 >> 4, c = i2 & 15;    /* r = k row 0..63, c = 16B block */   \
            const char* src = gB + (size_t)((kc) * BK + r) * 2048 + c * 16;         \
            CP_ASYNC16(stg + PART_A_BYTES + (uint32_t)(r * 256 + ((c ^ (r & 7)) * 16)), src); \
        }                                                                           \
    }                                                                               \
    CP_COMMIT();

    float acc[4][4][4];
#pragma unroll
    for (int i = 0; i < 4; i++)
#pragma unroll
        for (int j = 0; j < 4; j++)
#pragma unroll
            for (int k = 0; k < 4; k++) acc[i][j][k] = 0.f;

    ISSUE_CHUNK(0, 0);
    ISSUE_CHUNK(1, 1);

    const int fr_row = lane & 15;
    const int fr_kb  = lane >> 4;
    // B trans-LDSM per-lane address parts: k_local within 16, and n 16B-block
    const int bk_loc = (lane & 7) + ((lane >> 3) & 1) * 8;   // 0..15
    const int bn_blk = (lane >> 4);                           // 0/1 -> +8 n

    for (int it = 0; it < NCHUNK; it++) {
        if (it < NCHUNK - 1) { CP_WAIT1(); } else { CP_WAIT0(); }
        __syncthreads();

        if (it + 2 < NCHUNK) { ISSUE_CHUNK(it + 2, (it + 2) % NSTAGE); }

        const uint32_t st  = sm + SM_STAGE + (it % NSTAGE) * STAGE_BYTES;
        const uint32_t stA = st;
        const uint32_t stB = st + PART_A_BYTES;

#pragma unroll
        for (int ks = 0; ks < 4; ks++) {
            const uint32_t kcol = (uint32_t)((ks * 2 + fr_kb) * 16);

            uint32_t a[4][4], b[4][2];
#pragma unroll
            for (int mi = 0; mi < 4; mi++) {
                uint32_t ad = sw128((uint32_t)((wm * 64 + mi * 16 + fr_row) * 128) + kcol);
                LDSM4(a[mi][0], a[mi][1], a[mi][2], a[mi][3], stA + ad);
            }
            // B: k-major tile, ldmatrix.trans. Each LDSM4T covers 16k x 16n.
#pragma unroll
            for (int pj = 0; pj < 2; pj++) {
                int k   = ks * 16 + bk_loc;                       // k row in tile
                int blk = wn * 4 + pj * 2 + bn_blk;               // 16B block (8 n)
                uint32_t ad = (uint32_t)(k * 256 + ((blk ^ (k & 7)) * 16));
                uint32_t r0, r1, r2, r3;
                LDSM4T(r0, r1, r2, r3, stB + ad);
                b[pj * 2][0]     = r0; b[pj * 2][1]     = r1;     // n sub 0-7
                b[pj * 2 + 1][0] = r2; b[pj * 2 + 1][1] = r3;     // n sub 8-15
            }

#pragma unroll
            for (int mi = 0; mi < 4; mi++)
#pragma unroll
                for (int ni = 0; ni < 4; ni++)
                    MMA_F16(acc[mi][ni], a[mi], b[ni]);
        }
    }

    // ---- epilogue: bias + scatter
#pragma unroll
    for (int mi = 0; mi < 4; mi++) {
        int m0   = wm * 64 + mi * 16 + (lane >> 2);
        int tok0 = toks[m0];
        int tok1 = toks[m0 + 8];
#pragma unroll
        for (int ni = 0; ni < 4; ni++) {
            int col = wn * 32 + ni * 8 + 2 * (lane & 3);
            float b0 = bias_s[col], b1 = bias_s[col + 1];
            if (tok0 >= 0) {
                float2 v = make_float2(acc[mi][ni][0] + b0, acc[mi][ni][1] + b1);
                *reinterpret_cast<float2*>(out + (size_t)tok0 * DIM_O + n0 + col) = v;
            }
            if (tok1 >= 0) {
                float2 v = make_float2(acc[mi][ni][2] + b0, acc[mi][ni][3] + b1);
                *reinterpret_cast<float2*>(out + (size_t)tok1 * DIM_O + n0 + col) = v;
            }
        }
    }
}

// ---------------- launch --------------------------------------------------------
extern "C" void kernel_launch(void* const* d_in, const int* in_sizes, int n_in,
                              void* d_out, int out_size) {
    const float* x    = (const float*)d_in[0];   // [T, D] fp32
    const int*   cid  = (const int*)d_in[1];     // [T] int32
    const float* wgt  = (const float*)d_in[2];   // [C, D, O] fp32
    const float* bias = (const float*)d_in[3];   // [C, O] fp32
    float*       out  = (float*)d_out;           // [T, O] fp32

    (void)in_sizes; (void)n_in; (void)out_size;

    cudaFuncSetAttribute(k_gemm_f16, cudaFuncAttributeMaxDynamicSharedMemorySize, SMEM_TOTAL);

    k_setup<<<1, 1024>>>(cid);
    k_convert<<<16384, 256>>>(wgt, x);

    dim3 grid(MAX_TILES, DIM_O / TN);   // 72 x 8; CTAs past g_n_tiles exit early
    k_gemm_f16<<<grid, 256, SMEM_TOTAL>>>(bias, out);
}

// round 10
// speedup vs baseline: 1.2039x; 1.0259x over previous
#include <cuda_runtime.h>
#include <cuda_fp16.h>
#include <cstdint>

// Problem constants (fixed by dataset: B=4, S=2048, D=1024, O=1024, C=8)
#define T_TOK 8192
#define DIM_D 1024
#define DIM_O 1024
#define N_CAT 8

#define TM 128
#define TN 128
#define BK 64                        // K per smem stage
#define NCHUNK (DIM_D / BK)          // 16
#define MAX_TILES (T_TOK / TM + N_CAT)

// ---------------- device scratch (no allocation allowed) --------------------
__device__ int g_perm[T_TOK];
__device__ int g_tile_cat[MAX_TILES];
__device__ int g_tile_row[MAX_TILES];
__device__ int g_tile_rows[MAX_TILES];
__device__ int g_n_tiles;

// fp16 operands. X in NATURAL token order (+TM zero pad rows for partial
// tiles; never written -> stay zero from module init). W in NATIVE [c][d][o].
__device__ __half g_Xh[(T_TOK + TM) * DIM_D];
__device__ __half g_Wh[N_CAT * DIM_D * DIM_O];

// ---------------- PTX helpers (baseline sm_80/75 features only) -------------
__device__ __forceinline__ uint32_t smem_u32(const void* p) {
    uint32_t a;
    asm("{ .reg .u64 t; cvta.to.shared.u64 t, %1; cvt.u32.u64 %0, t; }" : "=r"(a) : "l"(p));
    return a;
}

#define CP_ASYNC16(dst, src) \
    asm volatile("cp.async.cg.shared.global [%0], [%1], 16;" :: "r"(dst), "l"(src) : "memory")
#define CP_COMMIT() asm volatile("cp.async.commit_group;" ::: "memory")
#define CP_WAIT0()  asm volatile("cp.async.wait_group 0;" ::: "memory")
#define CP_WAIT1()  asm volatile("cp.async.wait_group 1;" ::: "memory")

#define LDSM4(r0, r1, r2, r3, addr)                                              \
    asm volatile("ldmatrix.sync.aligned.m8n8.x4.shared.b16 {%0,%1,%2,%3}, [%4];" \
                 : "=r"(r0), "=r"(r1), "=r"(r2), "=r"(r3) : "r"(addr))

#define LDSM4T(r0, r1, r2, r3, addr)                                                   \
    asm volatile("ldmatrix.sync.aligned.m8n8.x4.trans.shared.b16 {%0,%1,%2,%3}, [%4];" \
                 : "=r"(r0), "=r"(r1), "=r"(r2), "=r"(r3) : "r"(addr))

#define MMA_F16(c, a, b)                                                         \
    asm volatile("mma.sync.aligned.m16n8k16.row.col.f32.f16.f16.f32 "            \
                 "{%0,%1,%2,%3}, {%4,%5,%6,%7}, {%8,%9}, {%0,%1,%2,%3};"         \
                 : "+f"((c)[0]), "+f"((c)[1]), "+f"((c)[2]), "+f"((c)[3])        \
                 : "r"((a)[0]), "r"((a)[1]), "r"((a)[2]), "r"((a)[3]),           \
                   "r"((b)[0]), "r"((b)[1]))

__device__ __forceinline__ uint32_t sw128(uint32_t off) {
    return off ^ ((off >> 3) & 0x70);
}

// ---------------- single prologue kernel ------------------------------------
// block 0:              setup (atomic-free counting sort + tile descriptors)
// blocks [1, 8192]:     W stream convert fp32->fp16
// blocks (8192, 16384]: X stream convert fp32->fp16 (natural token order)
__global__ void k_prep(const int* __restrict__ cid,
                       const float* __restrict__ w,
                       const float* __restrict__ x) {
    __shared__ int s_cnt[N_CAT][256];
    __shared__ int s_exc[N_CAT][256];
    __shared__ int s_base[N_CAT];

    const int b   = blockIdx.x;
    const int tid = threadIdx.x;    // 256

    if (b == 0) {
        // ---- load 32 cids/thread, count into packed 8-bit lanes (max 32 fits)
        int cl[32];
        uint32_t p0 = 0, p1 = 0;
#pragma unroll
        for (int i = 0; i < 32; i++) {
            int c = cid[tid + i * 256] & (N_CAT - 1);
            cl[i] = c;
            if (c < 4) p0 += 1u << (c * 8); else p1 += 1u << ((c - 4) * 8);
        }
#pragma unroll
        for (int c = 0; c < 4; c++) {
            s_cnt[c][tid]     = (p0 >> (c * 8)) & 0xFF;
            s_cnt[c + 4][tid] = (p1 >> (c * 8)) & 0xFF;
        }
        __syncthreads();

        // ---- 8 warps: exclusive scan of 256 counts for one category each
        const int wid = tid >> 5, lane = tid & 31;
        int tot = 0;
        {
            int run = 0;
#pragma unroll
            for (int ch = 0; ch < 8; ch++) {
                int v0 = s_cnt[wid][ch * 32 + lane];
                int v = v0;
#pragma unroll
                for (int o = 1; o < 32; o <<= 1) {
                    int n = __shfl_up_sync(0xFFFFFFFFu, v, o);
                    if (lane >= o) v += n;
                }
                s_exc[wid][ch * 32 + lane] = run + v - v0;
                run += __shfl_sync(0xFFFFFFFFu, v, 31);
            }
            tot = run;
        }
        if (lane == 0) s_base[wid] = tot;   // temp: per-cat totals
        __syncthreads();

        // ---- thread 0: base offsets + tile descriptors
        if (tid == 0) {
            int off = 0, nt = 0;
            for (int c = 0; c < N_CAT; c++) {
                int cnt = s_base[c];
                s_base[c] = off;
                for (int r = 0; r < cnt; r += TM) {
                    g_tile_cat[nt]  = c;
                    g_tile_row[nt]  = off + r;
                    g_tile_rows[nt] = (cnt - r < TM) ? (cnt - r) : TM;
                    nt++;
                }
                off += cnt;
            }
            g_n_tiles = nt;
        }
        __syncthreads();

        // ---- place tokens: pos = base[c] + exc[c][tid] + running local rank
        p0 = 0; p1 = 0;
#pragma unroll
        for (int i = 0; i < 32; i++) {
            int c = cl[i];
            int run = (c < 4) ? ((p0 >> (c * 8)) & 0xFF) : ((p1 >> ((c - 4) * 8)) & 0xFF);
            g_perm[s_base[c] + s_exc[c][tid] + run] = tid + i * 256;
            if (c < 4) p0 += 1u << (c * 8); else p1 += 1u << ((c - 4) * 8);
        }
    } else if (b <= 8192) {
        const size_t i = ((size_t)(b - 1) * 256 + tid) * 4;
        float4 v = *reinterpret_cast<const float4*>(w + i);
        __half2 a2 = __floats2half2_rn(v.x, v.y);
        __half2 b2 = __floats2half2_rn(v.z, v.w);
        uint2 u;
        u.x = *reinterpret_cast<uint32_t*>(&a2);
        u.y = *reinterpret_cast<uint32_t*>(&b2);
        *reinterpret_cast<uint2*>(&g_Wh[i]) = u;
    } else {
        const size_t i = ((size_t)(b - 8193) * 256 + tid) * 4;
        float4 v = *reinterpret_cast<const float4*>(x + i);
        __half2 a2 = __floats2half2_rn(v.x, v.y);
        __half2 b2 = __floats2half2_rn(v.z, v.w);
        uint2 u;
        u.x = *reinterpret_cast<uint32_t*>(&a2);
        u.y = *reinterpret_cast<uint32_t*>(&b2);
        *reinterpret_cast<uint2*>(&g_Xh[i]) = u;
    }
}

// ---------------- fp16 mma.sync grouped GEMM --------------------------------
// smem: [0..512) toks, [512..1024) bias, [2048..) 3 stages of
// {A: 128 rows x 128B (sw128) | B: 64 k-rows x 256B (xor-8 16B-block swizzle)}
#define SM_TOKS   0
#define SM_BIAS   512
#define SM_STAGE  2048
#define PART_A_BYTES 16384
#define STAGE_BYTES  32768
#define NSTAGE 3
#define SMEM_TOTAL (SM_STAGE + NSTAGE * STAGE_BYTES)

__global__ __launch_bounds__(256, 2)
void k_gemm_f16(const float* __restrict__ bias, float* __restrict__ out) {
    const int tile = blockIdx.x;
    if (tile >= g_n_tiles) return;

    const int cat       = g_tile_cat[tile] & (N_CAT - 1);
    const int row_start = g_tile_row[tile];
    const int rows      = g_tile_rows[tile];
    const int n0        = blockIdx.y * TN;

    extern __shared__ char smem[];
    const uint32_t sm = smem_u32(smem);
    const int tid  = threadIdx.x;
    const int wid  = tid >> 5;
    const int lane = tid & 31;
    const int wm   = wid >> 2;        // 0..1 -> m offset wm*64
    const int wn   = wid & 3;         // 0..3 -> n offset wn*32

    int*   toks   = reinterpret_cast<int*>(smem + SM_TOKS);
    float* bias_s = reinterpret_cast<float*>(smem + SM_BIAS);
    if (tid < TM) toks[tid] = (tid < rows) ? g_perm[row_start + tid] : -1;
    if (tid >= 128) bias_s[tid - 128] = bias[cat * DIM_O + n0 + tid - 128];
    __syncthreads();   // toks needed by every thread's A row pointers

    // A row pointers (gathered; chunk-invariant). Padding -> zero row T_TOK+.
    const char* aRow[4];
#pragma unroll
    for (int t = 0; t < 4; t++) {
        int r   = (tid >> 3) + t * 32;
        int tok = toks[r];
        if (tok < 0) tok = T_TOK + r;   // zero pad row
        aRow[t] = reinterpret_cast<const char*>(g_Xh) + (size_t)tok * 2048 + (tid & 7) * 16;
    }
    const char* gB = reinterpret_cast<const char*>(g_Wh) + (((size_t)cat << 20) + n0) * 2;

    // chunk loader: A 128 rows x 8 x 16B + B 64 k-rows x 16 x 16B = 2048, 8/thread
#define ISSUE_CHUNK(kc, buf)                                                        \
    _Pragma("unroll")                                                               \
    for (int t = 0; t < 8; t++) {                                                   \
        uint32_t stg = sm + SM_STAGE + (buf) * STAGE_BYTES;                         \
        if (t < 4) {                                                                \
            int r = (tid >> 3) + t * 32, c = tid & 7;                               \
            const char* src = aRow[t] + (size_t)(kc) * 128;                         \
            CP_ASYNC16(stg + sw128((uint32_t)(r * 128 + c * 16)), src);             \
        } else {                                                                    \
            int i2 = tid + (t - 4) * 256;                                           \
            int r = i2 >> 4, c = i2 & 15;    /* r = k row 0..63, c = 16B block */   \
            const char* src = gB + (size_t)((kc) * BK + r) * 2048 + c * 16;         \
            CP_ASYNC16(stg + PART_A_BYTES + (uint32_t)(r * 256 + ((c ^ (r & 7)) * 16)), src); \
        }                                                                           \
    }                                                                               \
    CP_COMMIT();

    float acc[4][4][4];
#pragma unroll
    for (int i = 0; i < 4; i++)
#pragma unroll
        for (int j = 0; j < 4; j++)
#pragma unroll
            for (int k = 0; k < 4; k++) acc[i][j][k] = 0.f;

    ISSUE_CHUNK(0, 0);
    ISSUE_CHUNK(1, 1);

    const int fr_row = lane & 15;
    const int fr_kb  = lane >> 4;
    const int bk_loc = (lane & 7) + ((lane >> 3) & 1) * 8;   // 0..15
    const int bn_blk = (lane >> 4);                           // 0/1 -> +8 n

    for (int it = 0; it < NCHUNK; it++) {
        if (it < NCHUNK - 1) { CP_WAIT1(); } else { CP_WAIT0(); }
        __syncthreads();

        if (it + 2 < NCHUNK) { ISSUE_CHUNK(it + 2, (it + 2) % NSTAGE); }

        const uint32_t st  = sm + SM_STAGE + (it % NSTAGE) * STAGE_BYTES;
        const uint32_t stA = st;
        const uint32_t stB = st + PART_A_BYTES;

#pragma unroll
        for (int ks = 0; ks < 4; ks++) {
            const uint32_t kcol = (uint32_t)((ks * 2 + fr_kb) * 16);

            uint32_t a[4][4], b[4][2];
#pragma unroll
            for (int mi = 0; mi < 4; mi++) {
                uint32_t ad = sw128((uint32_t)((wm * 64 + mi * 16 + fr_row) * 128) + kcol);
                LDSM4(a[mi][0], a[mi][1], a[mi][2], a[mi][3], stA + ad);
            }
#pragma unroll
            for (int pj = 0; pj < 2; pj++) {
                int k   = ks * 16 + bk_loc;
                int blk = wn * 4 + pj * 2 + bn_blk;
                uint32_t ad = (uint32_t)(k * 256 + ((blk ^ (k & 7)) * 16));
                uint32_t r0, r1, r2, r3;
                LDSM4T(r0, r1, r2, r3, stB + ad);
                b[pj * 2][0]     = r0; b[pj * 2][1]     = r1;
                b[pj * 2 + 1][0] = r2; b[pj * 2 + 1][1] = r3;
            }

#pragma unroll
            for (int mi = 0; mi < 4; mi++)
#pragma unroll
                for (int ni = 0; ni < 4; ni++)
                    MMA_F16(acc[mi][ni], a[mi], b[ni]);
        }
    }

    // ---- epilogue: bias + scatter
#pragma unroll
    for (int mi = 0; mi < 4; mi++) {
        int m0   = wm * 64 + mi * 16 + (lane >> 2);
        int tok0 = toks[m0];
        int tok1 = toks[m0 + 8];
#pragma unroll
        for (int ni = 0; ni < 4; ni++) {
            int col = wn * 32 + ni * 8 + 2 * (lane & 3);
            float b0 = bias_s[col], b1 = bias_s[col + 1];
            if (tok0 >= 0) {
                float2 v = make_float2(acc[mi][ni][0] + b0, acc[mi][ni][1] + b1);
                *reinterpret_cast<float2*>(out + (size_t)tok0 * DIM_O + n0 + col) = v;
            }
            if (tok1 >= 0) {
                float2 v = make_float2(acc[mi][ni][2] + b0, acc[mi][ni][3] + b1);
                *reinterpret_cast<float2*>(out + (size_t)tok1 * DIM_O + n0 + col) = v;
            }
        }
    }
}

// ---------------- launch --------------------------------------------------------
extern "C" void kernel_launch(void* const* d_in, const int* in_sizes, int n_in,
                              void* d_out, int out_size) {
    const float* x    = (const float*)d_in[0];   // [T, D] fp32
    const int*   cid  = (const int*)d_in[1];     // [T] int32
    const float* wgt  = (const float*)d_in[2];   // [C, D, O] fp32
    const float* bias = (const float*)d_in[3];   // [C, O] fp32
    float*       out  = (float*)d_out;           // [T, O] fp32

    (void)in_sizes; (void)n_in; (void)out_size;

    cudaFuncSetAttribute(k_gemm_f16, cudaFuncAttributeMaxDynamicSharedMemorySize, SMEM_TOTAL);

    k_prep<<<16385, 256>>>(cid, wgt, x);

    dim3 grid(MAX_TILES, DIM_O / TN);   // 72 x 8; CTAs past g_n_tiles exit early
    k_gemm_f16<<<grid, 256, SMEM_TOTAL>>>(bias, out);
}